// round 13
// baseline (speedup 1.0000x reference)
#include <cuda_runtime.h>
#include <cstdint>
#include <cfloat>
#include <math.h>

// ---------------- problem constants ----------------
#define TB 2
#define TS 512
#define TD 1024
#define NTOK (TB * TS)          // 1024 tokens
#define N_QK 2048
#define N_V 2048
#define N_KNOW 8192
#define KC_QK 48                // MAX_K_QK * CAND_MULT
#define KC_V 48
#define KC_KNOW 96
#define KS_QK 16
#define KS_V 16
#define KS_KNOW 32
#define CAPN 512                // compact buffer capacity

// output layout (flattened tuple, fp32)
#define OFF_GQ 0
#define OFF_GK (NTOK * KC_QK)                 // 49152
#define OFF_GV (2 * NTOK * KC_QK)             // 98304
#define OFF_IQK (3 * NTOK * KC_QK)            // 147456
#define OFF_IV (4 * NTOK * KC_QK)             // 196608
#define OFF_LATTN (5 * NTOK * KC_QK)          // 245760
#define OFF_GKN (OFF_LATTN + 1)               // 245761
#define OFF_IKN (OFF_GKN + NTOK * KC_KNOW)    // 344065
#define OFF_LKNOW (OFF_IKN + NTOK * KC_KNOW)  // 442369

// scratch: per-token projections + per-token/table loss partials
__device__ float g_posv[NTOK * 10];
__device__ float g_loss_q[NTOK];
__device__ float g_loss_v[NTOK];
__device__ float g_loss_kn[NTOK];

// ---------------- reduction helpers ----------------
__device__ __forceinline__ float warp_red_sum(float v) {
#pragma unroll
    for (int o = 16; o > 0; o >>= 1) v += __shfl_down_sync(0xffffffffu, v, o);
    return v;
}

__device__ __forceinline__ double warp_red_sum_d(double v) {
#pragma unroll
    for (int o = 16; o > 0; o >>= 1) v += __shfl_down_sync(0xffffffffu, v, o);
    return v;
}

__device__ __forceinline__ float block_red_sum(float v, float* red) {
    int lane = threadIdx.x & 31, w = threadIdx.x >> 5;
    v = warp_red_sum(v);
    if (lane == 0) red[w] = v;
    __syncthreads();
    if (w == 0) {
        float t = (lane < 8) ? red[lane] : 0.0f;
#pragma unroll
        for (int o = 4; o > 0; o >>= 1) t += __shfl_down_sync(0xffffffffu, t, o);
        if (lane == 0) red[0] = t;
    }
    __syncthreads();
    float r = red[0];
    __syncthreads();
    return r;
}

__device__ __forceinline__ int block_red_sum_i(int v, int* red) {
    int lane = threadIdx.x & 31, w = threadIdx.x >> 5;
#pragma unroll
    for (int o = 16; o > 0; o >>= 1) v += __shfl_down_sync(0xffffffffu, v, o);
    if (lane == 0) red[w] = v;
    __syncthreads();
    if (w == 0) {
        int t = (lane < 8) ? red[lane] : 0;
#pragma unroll
        for (int o = 4; o > 0; o >>= 1) t += __shfl_down_sync(0xffffffffu, t, o);
        if (lane == 0) red[0] = t;
    }
    __syncthreads();
    int r = red[0];
    __syncthreads();
    return r;
}

__device__ __forceinline__ float block_red_min(float v, float* red) {
    int lane = threadIdx.x & 31, w = threadIdx.x >> 5;
#pragma unroll
    for (int o = 16; o > 0; o >>= 1) v = fminf(v, __shfl_down_sync(0xffffffffu, v, o));
    if (lane == 0) red[w] = v;
    __syncthreads();
    if (w == 0) {
        float t = (lane < 8) ? red[lane] : FLT_MAX;
#pragma unroll
        for (int o = 4; o > 0; o >>= 1) t = fminf(t, __shfl_down_sync(0xffffffffu, t, o));
        if (lane == 0) red[0] = t;
    }
    __syncthreads();
    float r = red[0];
    __syncthreads();
    return r;
}

__device__ __forceinline__ float block_red_max(float v, float* red) {
    int lane = threadIdx.x & 31, w = threadIdx.x >> 5;
#pragma unroll
    for (int o = 16; o > 0; o >>= 1) v = fmaxf(v, __shfl_down_sync(0xffffffffu, v, o));
    if (lane == 0) red[w] = v;
    __syncthreads();
    if (w == 0) {
        float t = (lane < 8) ? red[lane] : -FLT_MAX;
#pragma unroll
        for (int o = 4; o > 0; o >>= 1) t = fmaxf(t, __shfl_down_sync(0xffffffffu, t, o));
        if (lane == 0) red[0] = t;
    }
    __syncthreads();
    float r = red[0];
    __syncthreads();
    return r;
}

__device__ __forceinline__ void resolve_proj(int o,
    const float* W_pos_qk, const float* b_pos_qk,
    const float* W_pos_v,  const float* b_pos_v,
    const float* W_pos_know, const float* b_pos_know,
    const float* W_tau_attn, const float* b_tau_attn,
    const float* W_tau_know, const float* b_tau_know,
    const float** W, const float** bp, int* st, int* col) {
    if (o < 2)      { *W = W_pos_qk;   *bp = b_pos_qk;   *st = 2; *col = o;     }
    else if (o < 4) { *W = W_pos_v;    *bp = b_pos_v;    *st = 2; *col = o - 2; }
    else if (o < 6) { *W = W_pos_know; *bp = b_pos_know; *st = 2; *col = o - 4; }
    else if (o < 9) { *W = W_tau_attn; *bp = b_tau_attn; *st = 3; *col = o - 6; }
    else            { *W = W_tau_know; *bp = b_tau_know; *st = 1; *col = 0;     }
}

// ---------------- pos/tau pre-kernel: one block per token ----------------
// EXACT sliced1x4 arithmetic from the R12 passing kernel (bit-identical).
__global__ void __launch_bounds__(64)
router_pos(const float* __restrict__ x,
           const float* __restrict__ W_pos_qk, const float* __restrict__ b_pos_qk,
           const float* __restrict__ W_pos_v,  const float* __restrict__ b_pos_v,
           const float* __restrict__ W_pos_know, const float* __restrict__ b_pos_know,
           const float* __restrict__ W_tau_attn, const float* __restrict__ b_tau_attn,
           const float* __restrict__ W_tau_know, const float* __restrict__ b_tau_know) {
    __shared__ __align__(16) float xs[TD];
    __shared__ float slice_part[10][4];
    const int tid = threadIdx.x;
    const int t   = blockIdx.x;

    for (int d = tid; d < TD; d += 64) xs[d] = x[(size_t)t * TD + d];
    __syncthreads();

    if (tid < 40) {
        const int o = tid >> 2;
        const int s = tid & 3;
        const float* W; const float* bp; int st, col;
        resolve_proj(o, W_pos_qk, b_pos_qk, W_pos_v, b_pos_v, W_pos_know,
                     b_pos_know, W_tau_attn, b_tau_attn, W_tau_know, b_tau_know,
                     &W, &bp, &st, &col);
        float acc = 0.0f;
        #pragma unroll 8
        for (int j = 0; j < 256; ++j) {
            int k = s + (j << 2);
            acc = fmaf(xs[k], __ldg(W + k * st + col), acc);
        }
        slice_part[o][s] = acc;
    }
    __syncthreads();
    if (tid < 10) {
        const int o = tid;
        const float* W; const float* bp; int st, col;
        resolve_proj(o, W_pos_qk, b_pos_qk, W_pos_v, b_pos_v, W_pos_know,
                     b_pos_know, W_tau_attn, b_tau_attn, W_tau_know, b_tau_know,
                     &W, &bp, &st, &col);
        float acc = __fadd_rn(__fadd_rn(slice_part[o][0], slice_part[o][1]),
                              __fadd_rn(slice_part[o][2], slice_part[o][3]));
        g_posv[t * 10 + o] = __fadd_rn(acc, __ldg(bp + col));
    }
}

// ---------------- main kernel: one block per (token, table) ----------------
__global__ void __launch_bounds__(256)
router_tab(const float* __restrict__ x,
           const float* __restrict__ neuron_pos,
           const float* __restrict__ qk_neurons,
           const float* __restrict__ v_neurons,
           const float* __restrict__ know_neurons,
           float* __restrict__ out) {
    __shared__ __align__(16) float xsd[TD];           // x / 0.9 row
    __shared__ unsigned int sdist[N_KNOW];            // dist bits (32 KB max)
    __shared__ unsigned long long cbuf[CAPN];
    __shared__ int   sel_idx[KC_KNOW];
    __shared__ float sel_dist[KC_KNOW];
    __shared__ float sc[KC_KNOW];
    __shared__ float egb[KC_KNOW];
    __shared__ float redf[8];
    __shared__ int   redi[8];
    __shared__ unsigned int s_T;
    __shared__ int s_done;
    __shared__ int s_cnt;

    const int tid  = threadIdx.x;
    const int lane = tid & 31;
    const int warp = tid >> 5;
    const int t    = blockIdx.x;
    const int tab  = blockIdx.y;

    // x / 0.9 row (identical per-element __fdiv_rn as the passing kernel)
    for (int d = tid; d < TD; d += 256)
        xsd[d] = __fdiv_rn(x[(size_t)t * TD + d], 0.9f);
    __syncthreads();

    int N, KC, KSEL, idxoff;
    const float* npos; const float* neur;
    float px, py;
    if (tab == 0) {
        N = N_QK; KC = KC_QK; KSEL = KS_QK; idxoff = OFF_IQK;
        npos = neuron_pos; neur = qk_neurons;
        px = g_posv[t * 10 + 0]; py = g_posv[t * 10 + 1];
    } else if (tab == 1) {
        N = N_V; KC = KC_V; KSEL = KS_V; idxoff = OFF_IV;
        npos = neuron_pos + 2 * N_QK; neur = v_neurons;
        px = g_posv[t * 10 + 2]; py = g_posv[t * 10 + 3];
    } else {
        N = N_KNOW; KC = KC_KNOW; KSEL = KS_KNOW; idxoff = OFF_IKN;
        npos = neuron_pos + 2 * (N_QK + N_V); neur = know_neurons;
        px = g_posv[t * 10 + 4]; py = g_posv[t * 10 + 5];
    }

    // distances: strict fp32 (mul, mul, add — no contraction)
    float lsum = 0.0f;
    const float2* np2 = (const float2*)npos;
    for (int i = tid; i < N; i += 256) {
        float2 p = __ldg(np2 + i);
        float dx = __fsub_rn(px, p.x);
        float dy = __fsub_rn(py, p.y);
        float dist = __fadd_rn(__fmul_rn(dx, dx), __fmul_rn(dy, dy));
        sdist[i] = __float_as_uint(dist);
        lsum += dist;
    }
    float dsum = block_red_sum(lsum, redf);

    // bisection for threshold T with KC <= count(d<=T) <= CAPN
    // (any T in the window yields the same sorted top-KC — shape-independent)
    if (tid == 0) {
        float mean = dsum / (float)N;
        float T0 = 4.0f * mean * (float)KC / (float)N;
        unsigned int tb = __float_as_uint(T0);
        if (tb == 0u || tb >= 0x7F800000u) tb = 0x3F800000u;
        s_T = tb; s_done = 0;
    }
    unsigned int lo = 0u, hi = 0x7F800000u;
    for (int it = 0; it < 40; ++it) {
        __syncthreads();
        if (s_done) break;
        unsigned int T = s_T;
        int c = 0;
        for (int i = tid; i < N; i += 256) c += (sdist[i] <= T);
        c = block_red_sum_i(c, redi);
        if (tid == 0) {
            if (c >= KC && c <= CAPN) s_done = 1;
            else if (c < KC) { lo = T; s_T = lo + ((hi - lo) >> 1); }
            else             { hi = T; s_T = lo + ((hi - lo) >> 1); }
        }
    }
    __syncthreads();

    // compact
    if (tid == 0) s_cnt = 0;
    __syncthreads();
    unsigned int T = s_T;
    for (int i = tid; i < N; i += 256) {
        unsigned int db = sdist[i];
        if (db <= T) {
            int pos = atomicAdd(&s_cnt, 1);
            if (pos < CAPN)
                cbuf[pos] = ((unsigned long long)db << 32) | (unsigned int)i;
        }
    }
    __syncthreads();
    int cnt = s_cnt; if (cnt > CAPN) cnt = CAPN;
    int P = 64; while (P < cnt) P <<= 1;
    for (int i = cnt + tid; i < P; i += 256) cbuf[i] = 0xFFFFFFFFFFFFFFFFull;
    __syncthreads();

    // bitonic sort ascending (dist asc, idx asc) == JAX top_k order
    for (int k = 2; k <= P; k <<= 1) {
        for (int j = k >> 1; j > 0; j >>= 1) {
            for (int i = tid; i < P; i += 256) {
                int ixj = i ^ j;
                if (ixj > i) {
                    unsigned long long a = cbuf[i], b = cbuf[ixj];
                    bool up = ((i & k) == 0);
                    if ((a > b) == up) { cbuf[i] = b; cbuf[ixj] = a; }
                }
            }
            __syncthreads();
        }
    }

    if (tid < KC) {
        unsigned long long key = cbuf[tid];
        int idx = (int)(key & 0xFFFFFFFFu);
        sel_idx[tid]  = idx;
        sel_dist[tid] = __uint_as_float((unsigned int)(key >> 32));
        out[idxoff + t * KC + tid] = (float)idx;
    }
    __syncthreads();

    // gathered scores: warp per candidate, fp64 accumulation (bit-identical to R12)
    for (int j = warp; j < KC; j += 8) {
        const float4* nr  = (const float4*)(neur + (size_t)sel_idx[j] * TD);
        const float4* xv4 = (const float4*)xsd;
        double dacc = 0.0;
#pragma unroll
        for (int c4 = lane; c4 < TD / 4; c4 += 32) {
            float4 nv = __ldg(nr + c4);
            float4 xv = xv4[c4];
            double s4 = (double)xv.x * (double)nv.x;
            s4 = fma((double)xv.y, (double)nv.y, s4);
            s4 = fma((double)xv.z, (double)nv.z, s4);
            s4 = fma((double)xv.w, (double)nv.w, s4);
            dacc += s4;
        }
        dacc = warp_red_sum_d(dacc);
        if (lane == 0) sc[j] = (float)dacc;
    }
    __syncthreads();

    // gating (tab 0 produces gate_Q and gate_K with tau cols 0/1)
    int ngates = (tab == 0) ? 2 : 1;
    for (int g = 0; g < ngates; ++g) {
        float tau; int goff; int addloss;
        if (tab == 0)      { tau = g_posv[t * 10 + 6 + g]; goff = g ? OFF_GK : OFF_GQ; addloss = (g == 0); }
        else if (tab == 1) { tau = g_posv[t * 10 + 8];     goff = OFF_GV;              addloss = 1; }
        else               { tau = g_posv[t * 10 + 9];     goff = OFF_GKN;             addloss = 1; }

        if (tid < KC) {
            float raw  = sc[tid] - tau;
            float gate = (raw > 0.0f) ? raw : 1e-8f * expf(raw);
            egb[tid] = expf(gate) - 1.0f;
        }
        __syncthreads();

        float candv = FLT_MAX;
        if (tid < KC) {
            float mye = egb[tid];
            int cgt = 0;
            for (int l = 0; l < KC; ++l) cgt += (egb[l] > mye);
            if (cgt < KSEL) candv = mye;
        }
        float thresh = block_red_min(candv, redf);

        float kept = 0.0f;
        if (tid < KC) {
            float e = egb[tid];
            kept = (e >= thresh) ? e : 0.0f;
        }
        float ssum = block_red_sum(kept, redf);
        float smax = block_red_max(kept, redf);

        float lp = 0.0f;
        if (tid < KC) {
            float gateo = kept / (ssum + 1e-8f) * tanhf(smax);
            out[goff + t * KC + tid] = gateo;
            if (addloss) lp = gateo * sel_dist[tid];
        }
        float ls = block_red_sum(lp, redf);
        if (tid == 0 && addloss) {
            if (tab == 0)      g_loss_q[t]  = ls;
            else if (tab == 1) g_loss_v[t]  = ls;
            else               g_loss_kn[t] = ls;
        }
        __syncthreads();
    }
}

// deterministic scalar-loss reduction (same combine order as before:
// per-token (lsQ + lsV), then identical strided+tree token reduction)
__global__ void router_finalize(float* __restrict__ out) {
    __shared__ float redf[8];
    int tid = threadIdx.x;
    float a = 0.0f, k = 0.0f;
    for (int i = tid; i < NTOK; i += 256) {
        float tmp = g_loss_q[i] + g_loss_v[i];
        a += tmp;
        k += g_loss_kn[i];
    }
    a = block_red_sum(a, redf);
    k = block_red_sum(k, redf);
    if (tid == 0) {
        out[OFF_LATTN] = a / (float)(NTOK * KC_QK);
        out[OFF_LKNOW] = k / (float)(NTOK * KC_KNOW);
    }
}

extern "C" void kernel_launch(void* const* d_in, const int* in_sizes, int n_in,
                              void* d_out, int out_size) {
    (void)in_sizes; (void)n_in; (void)out_size;
    router_pos<<<NTOK, 64>>>(
        (const float*)d_in[0],
        (const float*)d_in[5],  (const float*)d_in[6],
        (const float*)d_in[7],  (const float*)d_in[8],
        (const float*)d_in[9],  (const float*)d_in[10],
        (const float*)d_in[11], (const float*)d_in[12],
        (const float*)d_in[13], (const float*)d_in[14]);
    dim3 grid(NTOK, 3);
    router_tab<<<grid, 256>>>(
        (const float*)d_in[0],  (const float*)d_in[1],  (const float*)d_in[2],
        (const float*)d_in[3],  (const float*)d_in[4],
        (float*)d_out);
    router_finalize<<<1, 256>>>((float*)d_out);
}

// round 14
// speedup vs baseline: 7.2083x; 7.2083x over previous
#include <cuda_runtime.h>
#include <cstdint>
#include <cfloat>
#include <math.h>

// ---------------- problem constants ----------------
#define TB 2
#define TS 512
#define TD 1024
#define NTOK (TB * TS)          // 1024 tokens
#define N_QK 2048
#define N_V 2048
#define N_KNOW 8192
#define KC_QK 48                // MAX_K_QK * CAND_MULT
#define KC_V 48
#define KC_KNOW 96
#define KS_QK 16
#define KS_V 16
#define KS_KNOW 32
#define CAPN 512                // compact buffer capacity

// output layout (flattened tuple, fp32)
#define OFF_GQ 0
#define OFF_GK (NTOK * KC_QK)                 // 49152
#define OFF_GV (2 * NTOK * KC_QK)             // 98304
#define OFF_IQK (3 * NTOK * KC_QK)            // 147456
#define OFF_IV (4 * NTOK * KC_QK)             // 196608
#define OFF_LATTN (5 * NTOK * KC_QK)          // 245760
#define OFF_GKN (OFF_LATTN + 1)               // 245761
#define OFF_IKN (OFF_GKN + NTOK * KC_KNOW)    // 344065
#define OFF_LKNOW (OFF_IKN + NTOK * KC_KNOW)  // 442369

// scratch: per-token projections + per-token/table loss partials
__device__ float g_posv[NTOK * 10];
__device__ float g_loss_q[NTOK];
__device__ float g_loss_v[NTOK];
__device__ float g_loss_kn[NTOK];

// ---------------- reduction helpers ----------------
__device__ __forceinline__ float warp_red_sum(float v) {
#pragma unroll
    for (int o = 16; o > 0; o >>= 1) v += __shfl_down_sync(0xffffffffu, v, o);
    return v;
}

__device__ __forceinline__ float block_red_sum(float v, float* red) {
    int lane = threadIdx.x & 31, w = threadIdx.x >> 5;
    v = warp_red_sum(v);
    if (lane == 0) red[w] = v;
    __syncthreads();
    if (w == 0) {
        float t = (lane < 8) ? red[lane] : 0.0f;
#pragma unroll
        for (int o = 4; o > 0; o >>= 1) t += __shfl_down_sync(0xffffffffu, t, o);
        if (lane == 0) red[0] = t;
    }
    __syncthreads();
    float r = red[0];
    __syncthreads();
    return r;
}

__device__ __forceinline__ int block_red_sum_i(int v, int* red) {
    int lane = threadIdx.x & 31, w = threadIdx.x >> 5;
#pragma unroll
    for (int o = 16; o > 0; o >>= 1) v += __shfl_down_sync(0xffffffffu, v, o);
    if (lane == 0) red[w] = v;
    __syncthreads();
    if (w == 0) {
        int t = (lane < 8) ? red[lane] : 0;
#pragma unroll
        for (int o = 4; o > 0; o >>= 1) t += __shfl_down_sync(0xffffffffu, t, o);
        if (lane == 0) red[0] = t;
    }
    __syncthreads();
    int r = red[0];
    __syncthreads();
    return r;
}

__device__ __forceinline__ float block_red_min(float v, float* red) {
    int lane = threadIdx.x & 31, w = threadIdx.x >> 5;
#pragma unroll
    for (int o = 16; o > 0; o >>= 1) v = fminf(v, __shfl_down_sync(0xffffffffu, v, o));
    if (lane == 0) red[w] = v;
    __syncthreads();
    if (w == 0) {
        float t = (lane < 8) ? red[lane] : FLT_MAX;
#pragma unroll
        for (int o = 4; o > 0; o >>= 1) t = fminf(t, __shfl_down_sync(0xffffffffu, t, o));
        if (lane == 0) red[0] = t;
    }
    __syncthreads();
    float r = red[0];
    __syncthreads();
    return r;
}

__device__ __forceinline__ float block_red_max(float v, float* red) {
    int lane = threadIdx.x & 31, w = threadIdx.x >> 5;
#pragma unroll
    for (int o = 16; o > 0; o >>= 1) v = fmaxf(v, __shfl_down_sync(0xffffffffu, v, o));
    if (lane == 0) red[w] = v;
    __syncthreads();
    if (w == 0) {
        float t = (lane < 8) ? red[lane] : -FLT_MAX;
#pragma unroll
        for (int o = 4; o > 0; o >>= 1) t = fmaxf(t, __shfl_down_sync(0xffffffffu, t, o));
        if (lane == 0) red[0] = t;
    }
    __syncthreads();
    float r = red[0];
    __syncthreads();
    return r;
}

__device__ __forceinline__ void resolve_proj(int o,
    const float* W_pos_qk, const float* b_pos_qk,
    const float* W_pos_v,  const float* b_pos_v,
    const float* W_pos_know, const float* b_pos_know,
    const float* W_tau_attn, const float* b_tau_attn,
    const float* W_tau_know, const float* b_tau_know,
    const float** W, const float** bp, int* st, int* col) {
    if (o < 2)      { *W = W_pos_qk;   *bp = b_pos_qk;   *st = 2; *col = o;     }
    else if (o < 4) { *W = W_pos_v;    *bp = b_pos_v;    *st = 2; *col = o - 2; }
    else if (o < 6) { *W = W_pos_know; *bp = b_pos_know; *st = 2; *col = o - 4; }
    else if (o < 9) { *W = W_tau_attn; *bp = b_tau_attn; *st = 3; *col = o - 6; }
    else            { *W = W_tau_know; *bp = b_tau_know; *st = 1; *col = 0;     }
}

// ---------------- pos/tau pre-kernel: one block per token ----------------
// EXACT sliced1x4 arithmetic (bit-identical to the passing kernel).
__global__ void __launch_bounds__(64)
router_pos(const float* __restrict__ x,
           const float* __restrict__ W_pos_qk, const float* __restrict__ b_pos_qk,
           const float* __restrict__ W_pos_v,  const float* __restrict__ b_pos_v,
           const float* __restrict__ W_pos_know, const float* __restrict__ b_pos_know,
           const float* __restrict__ W_tau_attn, const float* __restrict__ b_tau_attn,
           const float* __restrict__ W_tau_know, const float* __restrict__ b_tau_know) {
    __shared__ __align__(16) float xs[TD];
    __shared__ float slice_part[10][4];
    const int tid = threadIdx.x;
    const int t   = blockIdx.x;

    for (int d = tid; d < TD; d += 64) xs[d] = x[(size_t)t * TD + d];
    __syncthreads();

    if (tid < 40) {
        const int o = tid >> 2;
        const int s = tid & 3;
        const float* W; const float* bp; int st, col;
        resolve_proj(o, W_pos_qk, b_pos_qk, W_pos_v, b_pos_v, W_pos_know,
                     b_pos_know, W_tau_attn, b_tau_attn, W_tau_know, b_tau_know,
                     &W, &bp, &st, &col);
        float acc = 0.0f;
        #pragma unroll 8
        for (int j = 0; j < 256; ++j) {
            int k = s + (j << 2);
            acc = fmaf(xs[k], __ldg(W + k * st + col), acc);
        }
        slice_part[o][s] = acc;
    }
    __syncthreads();
    if (tid < 10) {
        const int o = tid;
        const float* W; const float* bp; int st, col;
        resolve_proj(o, W_pos_qk, b_pos_qk, W_pos_v, b_pos_v, W_pos_know,
                     b_pos_know, W_tau_attn, b_tau_attn, W_tau_know, b_tau_know,
                     &W, &bp, &st, &col);
        float acc = __fadd_rn(__fadd_rn(slice_part[o][0], slice_part[o][1]),
                              __fadd_rn(slice_part[o][2], slice_part[o][3]));
        g_posv[t * 10 + o] = __fadd_rn(acc, __ldg(bp + col));
    }
}

// ---------------- main kernel: one block per (token, table) ----------------
__global__ void __launch_bounds__(256)
router_tab(const float* __restrict__ x,
           const float* __restrict__ neuron_pos,
           const float* __restrict__ qk_neurons,
           const float* __restrict__ v_neurons,
           const float* __restrict__ know_neurons,
           float* __restrict__ out) {
    __shared__ __align__(16) float xsd[TD];           // x / 0.9 row
    __shared__ unsigned int sdist[N_KNOW];            // dist bits (32 KB max)
    __shared__ unsigned long long cbuf[CAPN];
    __shared__ int   sel_idx[KC_KNOW];
    __shared__ float sel_dist[KC_KNOW];
    __shared__ float sc[KC_KNOW];
    __shared__ float egb[KC_KNOW];
    __shared__ float redf[8];
    __shared__ int   redi[8];
    __shared__ unsigned int s_T;
    __shared__ int s_done;
    __shared__ int s_cnt;

    const int tid  = threadIdx.x;
    const int lane = tid & 31;
    const int warp = tid >> 5;
    const int t    = blockIdx.x;
    const int tab  = blockIdx.y;

    for (int d = tid; d < TD; d += 256)
        xsd[d] = __fdiv_rn(x[(size_t)t * TD + d], 0.9f);
    __syncthreads();

    int N, KC, KSEL, idxoff;
    const float* npos; const float* neur;
    float px, py;
    if (tab == 0) {
        N = N_QK; KC = KC_QK; KSEL = KS_QK; idxoff = OFF_IQK;
        npos = neuron_pos; neur = qk_neurons;
        px = g_posv[t * 10 + 0]; py = g_posv[t * 10 + 1];
    } else if (tab == 1) {
        N = N_V; KC = KC_V; KSEL = KS_V; idxoff = OFF_IV;
        npos = neuron_pos + 2 * N_QK; neur = v_neurons;
        px = g_posv[t * 10 + 2]; py = g_posv[t * 10 + 3];
    } else {
        N = N_KNOW; KC = KC_KNOW; KSEL = KS_KNOW; idxoff = OFF_IKN;
        npos = neuron_pos + 2 * (N_QK + N_V); neur = know_neurons;
        px = g_posv[t * 10 + 4]; py = g_posv[t * 10 + 5];
    }

    // distances: strict fp32 (mul, mul, add — no contraction)
    float lsum = 0.0f;
    const float2* np2 = (const float2*)npos;
    for (int i = tid; i < N; i += 256) {
        float2 p = __ldg(np2 + i);
        float dx = __fsub_rn(px, p.x);
        float dy = __fsub_rn(py, p.y);
        float dist = __fadd_rn(__fmul_rn(dx, dx), __fmul_rn(dy, dy));
        sdist[i] = __float_as_uint(dist);
        lsum += dist;
    }
    float dsum = block_red_sum(lsum, redf);

    // bisection for threshold T with KC <= count(d<=T) <= CAPN
    if (tid == 0) {
        float mean = dsum / (float)N;
        float T0 = 4.0f * mean * (float)KC / (float)N;
        unsigned int tb = __float_as_uint(T0);
        if (tb == 0u || tb >= 0x7F800000u) tb = 0x3F800000u;
        s_T = tb; s_done = 0;
    }
    unsigned int lo = 0u, hi = 0x7F800000u;
    for (int it = 0; it < 40; ++it) {
        __syncthreads();
        if (s_done) break;
        unsigned int T = s_T;
        int c = 0;
        for (int i = tid; i < N; i += 256) c += (sdist[i] <= T);
        c = block_red_sum_i(c, redi);
        if (tid == 0) {
            if (c >= KC && c <= CAPN) s_done = 1;
            else if (c < KC) { lo = T; s_T = lo + ((hi - lo) >> 1); }
            else             { hi = T; s_T = lo + ((hi - lo) >> 1); }
        }
    }
    __syncthreads();

    // compact
    if (tid == 0) s_cnt = 0;
    __syncthreads();
    unsigned int T = s_T;
    for (int i = tid; i < N; i += 256) {
        unsigned int db = sdist[i];
        if (db <= T) {
            int pos = atomicAdd(&s_cnt, 1);
            if (pos < CAPN)
                cbuf[pos] = ((unsigned long long)db << 32) | (unsigned int)i;
        }
    }
    __syncthreads();
    int cnt = s_cnt; if (cnt > CAPN) cnt = CAPN;
    int P = 64; while (P < cnt) P <<= 1;
    for (int i = cnt + tid; i < P; i += 256) cbuf[i] = 0xFFFFFFFFFFFFFFFFull;
    __syncthreads();

    // bitonic sort ascending (dist asc, idx asc) == JAX top_k order
    for (int k = 2; k <= P; k <<= 1) {
        for (int j = k >> 1; j > 0; j >>= 1) {
            for (int i = tid; i < P; i += 256) {
                int ixj = i ^ j;
                if (ixj > i) {
                    unsigned long long a = cbuf[i], b = cbuf[ixj];
                    bool up = ((i & k) == 0);
                    if ((a > b) == up) { cbuf[i] = b; cbuf[ixj] = a; }
                }
            }
            __syncthreads();
        }
    }

    if (tid < KC) {
        unsigned long long key = cbuf[tid];
        int idx = (int)(key & 0xFFFFFFFFu);
        sel_idx[tid]  = idx;
        sel_dist[tid] = __uint_as_float((unsigned int)(key >> 32));
        out[idxoff + t * KC + tid] = (float)idx;
    }
    __syncthreads();

    // gathered scores: fp32, warp per candidate — float4 loads, per-group
    // 4-FFMA chain, serial group accumulation, fp32 shfl tree.
    // (Score-shape noise proven non-flipping across R1/R4/R8; fp64 removed —
    // it was the throughput ceiling of the whole kernel.)
    for (int j = warp; j < KC; j += 8) {
        const float4* nr  = (const float4*)(neur + (size_t)sel_idx[j] * TD);
        const float4* xv4 = (const float4*)xsd;
        float acc = 0.0f;
#pragma unroll
        for (int c4 = lane; c4 < TD / 4; c4 += 32) {
            float4 nv = __ldg(nr + c4);
            float4 xv = xv4[c4];
            acc = fmaf(xv.x, nv.x, acc);
            acc = fmaf(xv.y, nv.y, acc);
            acc = fmaf(xv.z, nv.z, acc);
            acc = fmaf(xv.w, nv.w, acc);
        }
        acc = warp_red_sum(acc);
        if (lane == 0) sc[j] = acc;
    }
    __syncthreads();

    // gating (tab 0 produces gate_Q and gate_K with tau cols 0/1)
    int ngates = (tab == 0) ? 2 : 1;
    for (int g = 0; g < ngates; ++g) {
        float tau; int goff; int addloss;
        if (tab == 0)      { tau = g_posv[t * 10 + 6 + g]; goff = g ? OFF_GK : OFF_GQ; addloss = (g == 0); }
        else if (tab == 1) { tau = g_posv[t * 10 + 8];     goff = OFF_GV;              addloss = 1; }
        else               { tau = g_posv[t * 10 + 9];     goff = OFF_GKN;             addloss = 1; }

        if (tid < KC) {
            float raw  = sc[tid] - tau;
            float gate = (raw > 0.0f) ? raw : 1e-8f * expf(raw);
            egb[tid] = expf(gate) - 1.0f;
        }
        __syncthreads();

        float candv = FLT_MAX;
        if (tid < KC) {
            float mye = egb[tid];
            int cgt = 0;
            for (int l = 0; l < KC; ++l) cgt += (egb[l] > mye);
            if (cgt < KSEL) candv = mye;
        }
        float thresh = block_red_min(candv, redf);

        float kept = 0.0f;
        if (tid < KC) {
            float e = egb[tid];
            kept = (e >= thresh) ? e : 0.0f;
        }
        float ssum = block_red_sum(kept, redf);
        float smax = block_red_max(kept, redf);

        float lp = 0.0f;
        if (tid < KC) {
            float gateo = kept / (ssum + 1e-8f) * tanhf(smax);
            out[goff + t * KC + tid] = gateo;
            if (addloss) lp = gateo * sel_dist[tid];
        }
        float ls = block_red_sum(lp, redf);
        if (tid == 0 && addloss) {
            if (tab == 0)      g_loss_q[t]  = ls;
            else if (tab == 1) g_loss_v[t]  = ls;
            else               g_loss_kn[t] = ls;
        }
        __syncthreads();
    }
}

// deterministic scalar-loss reduction (same combine order as the passing run)
__global__ void router_finalize(float* __restrict__ out) {
    __shared__ float redf[8];
    int tid = threadIdx.x;
    float a = 0.0f, k = 0.0f;
    for (int i = tid; i < NTOK; i += 256) {
        float tmp = g_loss_q[i] + g_loss_v[i];
        a += tmp;
        k += g_loss_kn[i];
    }
    a = block_red_sum(a, redf);
    k = block_red_sum(k, redf);
    if (tid == 0) {
        out[OFF_LATTN] = a / (float)(NTOK * KC_QK);
        out[OFF_LKNOW] = k / (float)(NTOK * KC_KNOW);
    }
}

extern "C" void kernel_launch(void* const* d_in, const int* in_sizes, int n_in,
                              void* d_out, int out_size) {
    (void)in_sizes; (void)n_in; (void)out_size;
    router_pos<<<NTOK, 64>>>(
        (const float*)d_in[0],
        (const float*)d_in[5],  (const float*)d_in[6],
        (const float*)d_in[7],  (const float*)d_in[8],
        (const float*)d_in[9],  (const float*)d_in[10],
        (const float*)d_in[11], (const float*)d_in[12],
        (const float*)d_in[13], (const float*)d_in[14]);
    dim3 grid(NTOK, 3);
    router_tab<<<grid, 256>>>(
        (const float*)d_in[0],  (const float*)d_in[1],  (const float*)d_in[2],
        (const float*)d_in[3],  (const float*)d_in[4],
        (float*)d_out);
    router_finalize<<<1, 256>>>((float*)d_out);
}

// round 15
// speedup vs baseline: 8.5526x; 1.1865x over previous
#include <cuda_runtime.h>
#include <cstdint>
#include <cfloat>
#include <math.h>

// ---------------- problem constants ----------------
#define TB 2
#define TS 512
#define TD 1024
#define NTOK (TB * TS)          // 1024 tokens
#define N_QK 2048
#define N_V 2048
#define N_KNOW 8192
#define KC_QK 48                // MAX_K_QK * CAND_MULT
#define KC_V 48
#define KC_KNOW 96
#define KS_QK 16
#define KS_V 16
#define KS_KNOW 32
#define CAPN 512                // compact buffer capacity
#define TPB_POS 4               // tokens per router_pos block

// output layout (flattened tuple, fp32)
#define OFF_GQ 0
#define OFF_GK (NTOK * KC_QK)                 // 49152
#define OFF_GV (2 * NTOK * KC_QK)             // 98304
#define OFF_IQK (3 * NTOK * KC_QK)            // 147456
#define OFF_IV (4 * NTOK * KC_QK)             // 196608
#define OFF_LATTN (5 * NTOK * KC_QK)          // 245760
#define OFF_GKN (OFF_LATTN + 1)               // 245761
#define OFF_IKN (OFF_GKN + NTOK * KC_KNOW)    // 344065
#define OFF_LKNOW (OFF_IKN + NTOK * KC_KNOW)  // 442369

// scratch: per-token projections + per-token/table loss partials
__device__ float g_posv[NTOK * 10];
__device__ float g_loss_q[NTOK];
__device__ float g_loss_v[NTOK];
__device__ float g_loss_kn[NTOK];

// ---------------- reduction helpers ----------------
__device__ __forceinline__ float warp_red_sum(float v) {
#pragma unroll
    for (int o = 16; o > 0; o >>= 1) v += __shfl_down_sync(0xffffffffu, v, o);
    return v;
}

__device__ __forceinline__ float block_red_sum(float v, float* red) {
    int lane = threadIdx.x & 31, w = threadIdx.x >> 5;
    v = warp_red_sum(v);
    if (lane == 0) red[w] = v;
    __syncthreads();
    if (w == 0) {
        float t = (lane < 8) ? red[lane] : 0.0f;
#pragma unroll
        for (int o = 4; o > 0; o >>= 1) t += __shfl_down_sync(0xffffffffu, t, o);
        if (lane == 0) red[0] = t;
    }
    __syncthreads();
    float r = red[0];
    __syncthreads();
    return r;
}

__device__ __forceinline__ int block_red_sum_i(int v, int* red) {
    int lane = threadIdx.x & 31, w = threadIdx.x >> 5;
#pragma unroll
    for (int o = 16; o > 0; o >>= 1) v += __shfl_down_sync(0xffffffffu, v, o);
    if (lane == 0) red[w] = v;
    __syncthreads();
    if (w == 0) {
        int t = (lane < 8) ? red[lane] : 0;
#pragma unroll
        for (int o = 4; o > 0; o >>= 1) t += __shfl_down_sync(0xffffffffu, t, o);
        if (lane == 0) red[0] = t;
    }
    __syncthreads();
    int r = red[0];
    __syncthreads();
    return r;
}

__device__ __forceinline__ float block_red_min(float v, float* red) {
    int lane = threadIdx.x & 31, w = threadIdx.x >> 5;
#pragma unroll
    for (int o = 16; o > 0; o >>= 1) v = fminf(v, __shfl_down_sync(0xffffffffu, v, o));
    if (lane == 0) red[w] = v;
    __syncthreads();
    if (w == 0) {
        float t = (lane < 8) ? red[lane] : FLT_MAX;
#pragma unroll
        for (int o = 4; o > 0; o >>= 1) t = fminf(t, __shfl_down_sync(0xffffffffu, t, o));
        if (lane == 0) red[0] = t;
    }
    __syncthreads();
    float r = red[0];
    __syncthreads();
    return r;
}

__device__ __forceinline__ float block_red_max(float v, float* red) {
    int lane = threadIdx.x & 31, w = threadIdx.x >> 5;
#pragma unroll
    for (int o = 16; o > 0; o >>= 1) v = fmaxf(v, __shfl_down_sync(0xffffffffu, v, o));
    if (lane == 0) red[w] = v;
    __syncthreads();
    if (w == 0) {
        float t = (lane < 8) ? red[lane] : -FLT_MAX;
#pragma unroll
        for (int o = 4; o > 0; o >>= 1) t = fmaxf(t, __shfl_down_sync(0xffffffffu, t, o));
        if (lane == 0) red[0] = t;
    }
    __syncthreads();
    float r = red[0];
    __syncthreads();
    return r;
}

__device__ __forceinline__ void resolve_proj(int o,
    const float* W_pos_qk, const float* b_pos_qk,
    const float* W_pos_v,  const float* b_pos_v,
    const float* W_pos_know, const float* b_pos_know,
    const float* W_tau_attn, const float* b_tau_attn,
    const float* W_tau_know, const float* b_tau_know,
    const float** W, const float** bp, int* st, int* col) {
    if (o < 2)      { *W = W_pos_qk;   *bp = b_pos_qk;   *st = 2; *col = o;     }
    else if (o < 4) { *W = W_pos_v;    *bp = b_pos_v;    *st = 2; *col = o - 2; }
    else if (o < 6) { *W = W_pos_know; *bp = b_pos_know; *st = 2; *col = o - 4; }
    else if (o < 9) { *W = W_tau_attn; *bp = b_tau_attn; *st = 3; *col = o - 6; }
    else            { *W = W_tau_know; *bp = b_tau_know; *st = 1; *col = 0;     }
}

// ---------------- pos/tau pre-kernel: TPB_POS tokens per block ----------------
// Per-token chain arithmetic is BIT-IDENTICAL to the passing sliced1x4 form;
// the only change is ILP: one W load feeds TPB_POS independent accumulators.
__global__ void __launch_bounds__(64)
router_pos(const float* __restrict__ x,
           const float* __restrict__ W_pos_qk, const float* __restrict__ b_pos_qk,
           const float* __restrict__ W_pos_v,  const float* __restrict__ b_pos_v,
           const float* __restrict__ W_pos_know, const float* __restrict__ b_pos_know,
           const float* __restrict__ W_tau_attn, const float* __restrict__ b_tau_attn,
           const float* __restrict__ W_tau_know, const float* __restrict__ b_tau_know) {
    __shared__ __align__(16) float xs[TPB_POS][TD];
    __shared__ float slice_part[TPB_POS][10][4];
    const int tid = threadIdx.x;
    const int t0  = blockIdx.x * TPB_POS;

    // coalesced load of TPB_POS consecutive token rows (contiguous in x)
    {
        const float4* src = (const float4*)(x + (size_t)t0 * TD);
        float4* dst = (float4*)(&xs[0][0]);
        for (int i = tid; i < TPB_POS * TD / 4; i += 64) dst[i] = src[i];
    }
    __syncthreads();

    if (tid < 40) {
        const int o = tid >> 2;
        const int s = tid & 3;
        const float* W; const float* bp; int st, col;
        resolve_proj(o, W_pos_qk, b_pos_qk, W_pos_v, b_pos_v, W_pos_know,
                     b_pos_know, W_tau_attn, b_tau_attn, W_tau_know, b_tau_know,
                     &W, &bp, &st, &col);
        float acc0 = 0.0f, acc1 = 0.0f, acc2 = 0.0f, acc3 = 0.0f;
        #pragma unroll 8
        for (int j = 0; j < 256; ++j) {
            int k = s + (j << 2);
            float w = __ldg(W + k * st + col);
            acc0 = fmaf(xs[0][k], w, acc0);
            acc1 = fmaf(xs[1][k], w, acc1);
            acc2 = fmaf(xs[2][k], w, acc2);
            acc3 = fmaf(xs[3][k], w, acc3);
        }
        slice_part[0][o][s] = acc0;
        slice_part[1][o][s] = acc1;
        slice_part[2][o][s] = acc2;
        slice_part[3][o][s] = acc3;
    }
    __syncthreads();
    // combine: 40 outputs = TPB_POS tokens x 10 projections
    if (tid < TPB_POS * 10) {
        const int tok = tid / 10;
        const int o   = tid % 10;
        const float* W; const float* bp; int st, col;
        resolve_proj(o, W_pos_qk, b_pos_qk, W_pos_v, b_pos_v, W_pos_know,
                     b_pos_know, W_tau_attn, b_tau_attn, W_tau_know, b_tau_know,
                     &W, &bp, &st, &col);
        float acc = __fadd_rn(__fadd_rn(slice_part[tok][o][0], slice_part[tok][o][1]),
                              __fadd_rn(slice_part[tok][o][2], slice_part[tok][o][3]));
        g_posv[(t0 + tok) * 10 + o] = __fadd_rn(acc, __ldg(bp + col));
    }
}

// ---------------- main kernel: one block per (token, table) ----------------
__global__ void __launch_bounds__(256)
router_tab(const float* __restrict__ x,
           const float* __restrict__ neuron_pos,
           const float* __restrict__ qk_neurons,
           const float* __restrict__ v_neurons,
           const float* __restrict__ know_neurons,
           float* __restrict__ out) {
    __shared__ __align__(16) float xsd[TD];           // x / 0.9 row
    __shared__ unsigned int sdist[N_KNOW];            // dist bits (32 KB max)
    __shared__ unsigned long long cbuf[CAPN];
    __shared__ int   sel_idx[KC_KNOW];
    __shared__ float sel_dist[KC_KNOW];
    __shared__ float sc[KC_KNOW];
    __shared__ float egb[KC_KNOW];
    __shared__ float redf[8];
    __shared__ int   redi[8];
    __shared__ unsigned int s_T;
    __shared__ int s_done;
    __shared__ int s_cnt;

    const int tid  = threadIdx.x;
    const int lane = tid & 31;
    const int warp = tid >> 5;
    const int t    = blockIdx.x;
    const int tab  = blockIdx.y;

    for (int d = tid; d < TD; d += 256)
        xsd[d] = __fdiv_rn(x[(size_t)t * TD + d], 0.9f);
    __syncthreads();

    int N, KC, KSEL, idxoff;
    const float* npos; const float* neur;
    float px, py;
    if (tab == 0) {
        N = N_QK; KC = KC_QK; KSEL = KS_QK; idxoff = OFF_IQK;
        npos = neuron_pos; neur = qk_neurons;
        px = g_posv[t * 10 + 0]; py = g_posv[t * 10 + 1];
    } else if (tab == 1) {
        N = N_V; KC = KC_V; KSEL = KS_V; idxoff = OFF_IV;
        npos = neuron_pos + 2 * N_QK; neur = v_neurons;
        px = g_posv[t * 10 + 2]; py = g_posv[t * 10 + 3];
    } else {
        N = N_KNOW; KC = KC_KNOW; KSEL = KS_KNOW; idxoff = OFF_IKN;
        npos = neuron_pos + 2 * (N_QK + N_V); neur = know_neurons;
        px = g_posv[t * 10 + 4]; py = g_posv[t * 10 + 5];
    }

    // distances: strict fp32 (mul, mul, add — no contraction)
    float lsum = 0.0f;
    const float2* np2 = (const float2*)npos;
    for (int i = tid; i < N; i += 256) {
        float2 p = __ldg(np2 + i);
        float dx = __fsub_rn(px, p.x);
        float dy = __fsub_rn(py, p.y);
        float dist = __fadd_rn(__fmul_rn(dx, dx), __fmul_rn(dy, dy));
        sdist[i] = __float_as_uint(dist);
        lsum += dist;
    }
    float dsum = block_red_sum(lsum, redf);

    // bisection for threshold T with KC <= count(d<=T) <= CAPN
    if (tid == 0) {
        float mean = dsum / (float)N;
        float T0 = 4.0f * mean * (float)KC / (float)N;
        unsigned int tb = __float_as_uint(T0);
        if (tb == 0u || tb >= 0x7F800000u) tb = 0x3F800000u;
        s_T = tb; s_done = 0;
    }
    unsigned int lo = 0u, hi = 0x7F800000u;
    for (int it = 0; it < 40; ++it) {
        __syncthreads();
        if (s_done) break;
        unsigned int T = s_T;
        int c = 0;
        for (int i = tid; i < N; i += 256) c += (sdist[i] <= T);
        c = block_red_sum_i(c, redi);
        if (tid == 0) {
            if (c >= KC && c <= CAPN) s_done = 1;
            else if (c < KC) { lo = T; s_T = lo + ((hi - lo) >> 1); }
            else             { hi = T; s_T = lo + ((hi - lo) >> 1); }
        }
    }
    __syncthreads();

    // compact
    if (tid == 0) s_cnt = 0;
    __syncthreads();
    unsigned int T = s_T;
    for (int i = tid; i < N; i += 256) {
        unsigned int db = sdist[i];
        if (db <= T) {
            int pos = atomicAdd(&s_cnt, 1);
            if (pos < CAPN)
                cbuf[pos] = ((unsigned long long)db << 32) | (unsigned int)i;
        }
    }
    __syncthreads();
    int cnt = s_cnt; if (cnt > CAPN) cnt = CAPN;
    int P = 64; while (P < cnt) P <<= 1;
    for (int i = cnt + tid; i < P; i += 256) cbuf[i] = 0xFFFFFFFFFFFFFFFFull;
    __syncthreads();

    // bitonic sort ascending (dist asc, idx asc) == JAX top_k order
    for (int k = 2; k <= P; k <<= 1) {
        for (int j = k >> 1; j > 0; j >>= 1) {
            for (int i = tid; i < P; i += 256) {
                int ixj = i ^ j;
                if (ixj > i) {
                    unsigned long long a = cbuf[i], b = cbuf[ixj];
                    bool up = ((i & k) == 0);
                    if ((a > b) == up) { cbuf[i] = b; cbuf[ixj] = a; }
                }
            }
            __syncthreads();
        }
    }

    if (tid < KC) {
        unsigned long long key = cbuf[tid];
        int idx = (int)(key & 0xFFFFFFFFu);
        sel_idx[tid]  = idx;
        sel_dist[tid] = __uint_as_float((unsigned int)(key >> 32));
        out[idxoff + t * KC + tid] = (float)idx;
    }
    __syncthreads();

    // gathered scores: fp32, warp per candidate (same as passing R14)
    for (int j = warp; j < KC; j += 8) {
        const float4* nr  = (const float4*)(neur + (size_t)sel_idx[j] * TD);
        const float4* xv4 = (const float4*)xsd;
        float acc = 0.0f;
#pragma unroll
        for (int c4 = lane; c4 < TD / 4; c4 += 32) {
            float4 nv = __ldg(nr + c4);
            float4 xv = xv4[c4];
            acc = fmaf(xv.x, nv.x, acc);
            acc = fmaf(xv.y, nv.y, acc);
            acc = fmaf(xv.z, nv.z, acc);
            acc = fmaf(xv.w, nv.w, acc);
        }
        acc = warp_red_sum(acc);
        if (lane == 0) sc[j] = acc;
    }
    __syncthreads();

    // gating (tab 0 produces gate_Q and gate_K with tau cols 0/1)
    int ngates = (tab == 0) ? 2 : 1;
    for (int g = 0; g < ngates; ++g) {
        float tau; int goff; int addloss;
        if (tab == 0)      { tau = g_posv[t * 10 + 6 + g]; goff = g ? OFF_GK : OFF_GQ; addloss = (g == 0); }
        else if (tab == 1) { tau = g_posv[t * 10 + 8];     goff = OFF_GV;              addloss = 1; }
        else               { tau = g_posv[t * 10 + 9];     goff = OFF_GKN;             addloss = 1; }

        if (tid < KC) {
            float raw  = sc[tid] - tau;
            float gate = (raw > 0.0f) ? raw : 1e-8f * expf(raw);
            egb[tid] = expf(gate) - 1.0f;
        }
        __syncthreads();

        float candv = FLT_MAX;
        if (tid < KC) {
            float mye = egb[tid];
            int cgt = 0;
            for (int l = 0; l < KC; ++l) cgt += (egb[l] > mye);
            if (cgt < KSEL) candv = mye;
        }
        float thresh = block_red_min(candv, redf);

        float kept = 0.0f;
        if (tid < KC) {
            float e = egb[tid];
            kept = (e >= thresh) ? e : 0.0f;
        }
        float ssum = block_red_sum(kept, redf);
        float smax = block_red_max(kept, redf);

        float lp = 0.0f;
        if (tid < KC) {
            float gateo = kept / (ssum + 1e-8f) * tanhf(smax);
            out[goff + t * KC + tid] = gateo;
            if (addloss) lp = gateo * sel_dist[tid];
        }
        float ls = block_red_sum(lp, redf);
        if (tid == 0 && addloss) {
            if (tab == 0)      g_loss_q[t]  = ls;
            else if (tab == 1) g_loss_v[t]  = ls;
            else               g_loss_kn[t] = ls;
        }
        __syncthreads();
    }
}

// deterministic scalar-loss reduction (same combine order as the passing run)
__global__ void router_finalize(float* __restrict__ out) {
    __shared__ float redf[8];
    int tid = threadIdx.x;
    float a = 0.0f, k = 0.0f;
    for (int i = tid; i < NTOK; i += 256) {
        float tmp = g_loss_q[i] + g_loss_v[i];
        a += tmp;
        k += g_loss_kn[i];
    }
    a = block_red_sum(a, redf);
    k = block_red_sum(k, redf);
    if (tid == 0) {
        out[OFF_LATTN] = a / (float)(NTOK * KC_QK);
        out[OFF_LKNOW] = k / (float)(NTOK * KC_KNOW);
    }
}

extern "C" void kernel_launch(void* const* d_in, const int* in_sizes, int n_in,
                              void* d_out, int out_size) {
    (void)in_sizes; (void)n_in; (void)out_size;
    router_pos<<<NTOK / TPB_POS, 64>>>(
        (const float*)d_in[0],
        (const float*)d_in[5],  (const float*)d_in[6],
        (const float*)d_in[7],  (const float*)d_in[8],
        (const float*)d_in[9],  (const float*)d_in[10],
        (const float*)d_in[11], (const float*)d_in[12],
        (const float*)d_in[13], (const float*)d_in[14]);
    dim3 grid(NTOK, 3);
    router_tab<<<grid, 256>>>(
        (const float*)d_in[0],  (const float*)d_in[1],  (const float*)d_in[2],
        (const float*)d_in[3],  (const float*)d_in[4],
        (float*)d_out);
    router_finalize<<<1, 256>>>((float*)d_out);
}